// round 3
// baseline (speedup 1.0000x reference)
#include <cuda_runtime.h>
#include <cstdint>

#define M_SLOTS 10
#define HW      7744          // 88*88
#define HW4     1936          // HW/4 (float4 / ulonglong2 units)
#define ROWS    8192          // B*C
#define KC4     242           // chunk length in float4 units (1936/8)
#define NCH     8
#define RPB     32            // rows per block
#define NT      256           // threads per block (8 warps x 4 rows)

typedef unsigned long long u64;

// Partial scores scratch: [chunk][row][m]  (2.62 MB, every slot written every launch)
__device__ float g_part[NCH][ROWS][M_SLOTS];

__device__ __forceinline__ u64 fma2(u64 a, u64 b, u64 c) {
    u64 d;
    asm("fma.rn.f32x2 %0, %1, %2, %3;" : "=l"(d) : "l"(a), "l"(b), "l"(c));
    return d;
}

__device__ __forceinline__ u64 pack2(float v) {
    u64 t;
    asm("mov.b64 %0, {%1, %1};" : "=l"(t) : "f"(v));
    return t;
}

__device__ __forceinline__ float hsum2(u64 a) {
    float x, y;
    asm("mov.b64 {%0, %1}, %2;" : "=f"(x), "=f"(y) : "l"(a));
    return x + y;
}

// ---------------------------------------------------------------------------
// K1: partial scores.  grid = (ROWS/RPB, NCH) = 2048 blocks.  Each warp owns
// 4 rows exclusively; lanes stride the chunk's 242 float4s.  No __syncthreads.
// ---------------------------------------------------------------------------
__global__ __launch_bounds__(NT)
void k1_scores(const float* __restrict__ x, const float* __restrict__ mem) {
    const int tid  = threadIdx.x;
    const int lane = tid & 31;
    const int warp = tid >> 5;
    const int row0 = blockIdx.x * RPB + warp * 4;
    const int base4 = blockIdx.y * KC4;

    const ulonglong2* __restrict__ m2 = (const ulonglong2*)mem;
    const ulonglong2* __restrict__ xr0 = (const ulonglong2*)(x + (size_t)(row0 + 0) * HW) + base4;
    const ulonglong2* __restrict__ xr1 = (const ulonglong2*)(x + (size_t)(row0 + 1) * HW) + base4;
    const ulonglong2* __restrict__ xr2 = (const ulonglong2*)(x + (size_t)(row0 + 2) * HW) + base4;
    const ulonglong2* __restrict__ xr3 = (const ulonglong2*)(x + (size_t)(row0 + 3) * HW) + base4;

    u64 acc[4][M_SLOTS];
    #pragma unroll
    for (int r = 0; r < 4; r++)
        #pragma unroll
        for (int m = 0; m < M_SLOTS; m++) acc[r][m] = 0ull;

    for (int j = lane; j < KC4; j += 32) {
        ulonglong2 x0 = xr0[j];
        ulonglong2 x1 = xr1[j];
        ulonglong2 x2 = xr2[j];
        ulonglong2 x3 = xr3[j];
        #pragma unroll
        for (int m = 0; m < M_SLOTS; m++) {
            ulonglong2 w = __ldg(&m2[(size_t)m * HW4 + base4 + j]);
            acc[0][m] = fma2(x0.x, w.x, acc[0][m]);
            acc[1][m] = fma2(x1.x, w.x, acc[1][m]);
            acc[2][m] = fma2(x2.x, w.x, acc[2][m]);
            acc[3][m] = fma2(x3.x, w.x, acc[3][m]);
            acc[0][m] = fma2(x0.y, w.y, acc[0][m]);
            acc[1][m] = fma2(x1.y, w.y, acc[1][m]);
            acc[2][m] = fma2(x2.y, w.y, acc[2][m]);
            acc[3][m] = fma2(x3.y, w.y, acc[3][m]);
        }
    }

    // warp reduce, lane 0 stores partials
    #pragma unroll
    for (int r = 0; r < 4; r++) {
        #pragma unroll
        for (int m = 0; m < M_SLOTS; m++) {
            float v = hsum2(acc[r][m]);
            v += __shfl_xor_sync(0xFFFFFFFFu, v, 16);
            v += __shfl_xor_sync(0xFFFFFFFFu, v, 8);
            v += __shfl_xor_sync(0xFFFFFFFFu, v, 4);
            v += __shfl_xor_sync(0xFFFFFFFFu, v, 2);
            v += __shfl_xor_sync(0xFFFFFFFFu, v, 1);
            if (lane == 0) g_part[blockIdx.y][row0 + r][m] = v;
        }
    }
}

// ---------------------------------------------------------------------------
// K3: softmax (from partials) + value expansion.  Same 2048-block geometry.
// ---------------------------------------------------------------------------
__global__ __launch_bounds__(NT)
void k3_value(const float* __restrict__ mem, float* __restrict__ out) {
    __shared__ float p_s[RPB][M_SLOTS];

    const int tid  = threadIdx.x;
    const int lane = tid & 31;
    const int warp = tid >> 5;
    const int base4 = blockIdx.y * KC4;

    // first 32 threads: reduce 8 partials per row + softmax
    if (tid < RPB) {
        const int row = blockIdx.x * RPB + tid;
        float s[M_SLOTS];
        #pragma unroll
        for (int m = 0; m < M_SLOTS; m++) s[m] = 0.0f;
        #pragma unroll
        for (int c = 0; c < NCH; c++)
            #pragma unroll
            for (int m = 0; m < M_SLOTS; m++) s[m] += g_part[c][row][m];
        float mx = -1e30f;
        #pragma unroll
        for (int m = 0; m < M_SLOTS; m++) mx = fmaxf(mx, s[m]);
        float sum = 0.0f;
        #pragma unroll
        for (int m = 0; m < M_SLOTS; m++) { s[m] = __expf(s[m] - mx); sum += s[m]; }
        float inv = 1.0f / sum;
        #pragma unroll
        for (int m = 0; m < M_SLOTS; m++) p_s[tid][m] = s[m] * inv;
    }
    __syncthreads();

    const int row0 = blockIdx.x * RPB + warp * 4;
    u64 p2[4][M_SLOTS];
    #pragma unroll
    for (int r = 0; r < 4; r++)
        #pragma unroll
        for (int m = 0; m < M_SLOTS; m++)
            p2[r][m] = pack2(p_s[warp * 4 + r][m]);

    const ulonglong2* __restrict__ m2 = (const ulonglong2*)mem;
    ulonglong2* __restrict__ o0 = (ulonglong2*)(out + (size_t)(row0 + 0) * HW) + base4;
    ulonglong2* __restrict__ o1 = (ulonglong2*)(out + (size_t)(row0 + 1) * HW) + base4;
    ulonglong2* __restrict__ o2 = (ulonglong2*)(out + (size_t)(row0 + 2) * HW) + base4;
    ulonglong2* __restrict__ o3 = (ulonglong2*)(out + (size_t)(row0 + 3) * HW) + base4;

    for (int j = lane; j < KC4; j += 32) {
        u64 a0x = 0ull, a0y = 0ull, a1x = 0ull, a1y = 0ull;
        u64 a2x = 0ull, a2y = 0ull, a3x = 0ull, a3y = 0ull;
        #pragma unroll
        for (int m = 0; m < M_SLOTS; m++) {
            ulonglong2 w = __ldg(&m2[(size_t)m * HW4 + base4 + j]);
            a0x = fma2(p2[0][m], w.x, a0x);  a0y = fma2(p2[0][m], w.y, a0y);
            a1x = fma2(p2[1][m], w.x, a1x);  a1y = fma2(p2[1][m], w.y, a1y);
            a2x = fma2(p2[2][m], w.x, a2x);  a2y = fma2(p2[2][m], w.y, a2y);
            a3x = fma2(p2[3][m], w.x, a3x);  a3y = fma2(p2[3][m], w.y, a3y);
        }
        ulonglong2 v0; v0.x = a0x; v0.y = a0y; o0[j] = v0;
        ulonglong2 v1; v1.x = a1x; v1.y = a1y; o1[j] = v1;
        ulonglong2 v2; v2.x = a2x; v2.y = a2y; o2[j] = v2;
        ulonglong2 v3; v3.x = a3x; v3.y = a3y; o3[j] = v3;
    }
}

extern "C" void kernel_launch(void* const* d_in, const int* in_sizes, int n_in,
                              void* d_out, int out_size) {
    const float* x   = (const float*)d_in[0];   // [32,256,88,88]
    const float* mem = (const float*)d_in[1];   // [10,88,88]
    float* out = (float*)d_out;

    dim3 grid(ROWS / RPB, NCH);   // 256 x 8 = 2048 blocks
    k1_scores<<<grid, NT>>>(x, mem);
    k3_value<<<grid, NT>>>(mem, out);
}

// round 4
// speedup vs baseline: 1.1969x; 1.1969x over previous
#include <cuda_runtime.h>
#include <cstdint>

#define M_SLOTS 10
#define HW      7744          // 88*88
#define HW4     1936          // HW in float4 units
#define ROWS    8192          // B*C
#define KC4     242           // chunk length in float4 units (1936/8)
#define NCH     8
#define RPB     32            // rows per block
#define NT      256           // 8 warps x 4 rows

// Partial scores scratch: [row][chunk][m]  (2.62 MB; every slot written each launch)
__device__ float g_part[ROWS][NCH][M_SLOTS];

// ---------------------------------------------------------------------------
// K1: partial scores.  grid = (ROWS/RPB, NCH) = 2048 blocks.  Each warp owns
// 4 rows exclusively; lanes stride the chunk's 242 float4s.  No __syncthreads.
// Scalar FFMA, float accumulators (40 regs) -> no spills.
// ---------------------------------------------------------------------------
__global__ __launch_bounds__(NT)
void k1_scores(const float* __restrict__ x, const float* __restrict__ mem) {
    const int lane = threadIdx.x & 31;
    const int warp = threadIdx.x >> 5;
    const int row0 = blockIdx.x * RPB + warp * 4;
    const int base4 = blockIdx.y * KC4;

    const float4* __restrict__ m4 = (const float4*)mem;
    const float4* __restrict__ xr0 = (const float4*)(x + (size_t)(row0 + 0) * HW) + base4;
    const float4* __restrict__ xr1 = (const float4*)(x + (size_t)(row0 + 1) * HW) + base4;
    const float4* __restrict__ xr2 = (const float4*)(x + (size_t)(row0 + 2) * HW) + base4;
    const float4* __restrict__ xr3 = (const float4*)(x + (size_t)(row0 + 3) * HW) + base4;

    float acc[4][M_SLOTS];
    #pragma unroll
    for (int r = 0; r < 4; r++)
        #pragma unroll
        for (int m = 0; m < M_SLOTS; m++) acc[r][m] = 0.0f;

    for (int j = lane; j < KC4; j += 32) {
        float4 x0 = xr0[j];
        float4 x1 = xr1[j];
        float4 x2 = xr2[j];
        float4 x3 = xr3[j];
        #pragma unroll
        for (int m = 0; m < M_SLOTS; m++) {
            float4 w = __ldg(&m4[(size_t)m * HW4 + base4 + j]);
            acc[0][m] = fmaf(x0.x, w.x, fmaf(x0.y, w.y, fmaf(x0.z, w.z, fmaf(x0.w, w.w, acc[0][m]))));
            acc[1][m] = fmaf(x1.x, w.x, fmaf(x1.y, w.y, fmaf(x1.z, w.z, fmaf(x1.w, w.w, acc[1][m]))));
            acc[2][m] = fmaf(x2.x, w.x, fmaf(x2.y, w.y, fmaf(x2.z, w.z, fmaf(x2.w, w.w, acc[2][m]))));
            acc[3][m] = fmaf(x3.x, w.x, fmaf(x3.y, w.y, fmaf(x3.z, w.z, fmaf(x3.w, w.w, acc[3][m]))));
        }
    }

    // warp reduce; lane 0 stores the 40 partials for this warp's 4 rows
    #pragma unroll
    for (int r = 0; r < 4; r++) {
        #pragma unroll
        for (int m = 0; m < M_SLOTS; m++) {
            float v = acc[r][m];
            v += __shfl_xor_sync(0xFFFFFFFFu, v, 16);
            v += __shfl_xor_sync(0xFFFFFFFFu, v, 8);
            v += __shfl_xor_sync(0xFFFFFFFFu, v, 4);
            v += __shfl_xor_sync(0xFFFFFFFFu, v, 2);
            v += __shfl_xor_sync(0xFFFFFFFFu, v, 1);
            if (lane == 0) g_part[row0 + r][blockIdx.y][m] = v;
        }
    }
}

// ---------------------------------------------------------------------------
// K3: softmax + value expansion.  Same 2048-block geometry, NO barriers:
// lanes 0..3 of each warp do the softmax for the warp's 4 rows (contiguous
// 320B reads), then 40 shfl broadcasts distribute p[r][m] to all lanes.
// ---------------------------------------------------------------------------
__global__ __launch_bounds__(NT)
void k3_value(const float* __restrict__ mem, float* __restrict__ out) {
    const int lane = threadIdx.x & 31;
    const int warp = threadIdx.x >> 5;
    const int row0 = blockIdx.x * RPB + warp * 4;
    const int base4 = blockIdx.y * KC4;

    // lanes 0..3: softmax for row0+lane
    float p_loc[M_SLOTS];
    {
        const int r = (lane < 4) ? lane : 0;      // inactive lanes compute garbage (unused)
        const float4* pp = (const float4*)&g_part[row0 + r][0][0];  // 80 floats = 20 float4
        float s[M_SLOTS];
        #pragma unroll
        for (int m = 0; m < M_SLOTS; m++) s[m] = 0.0f;
        #pragma unroll
        for (int c = 0; c < NCH; c++) {
            // chunk c occupies floats [c*10, c*10+10) = float4s not aligned to m;
            // read scalar: 10 floats per chunk (L1-resident after first touch)
            const float* pc = &g_part[row0 + r][c][0];
            #pragma unroll
            for (int m = 0; m < M_SLOTS; m++) s[m] += pc[m];
        }
        (void)pp;
        float mx = -1e30f;
        #pragma unroll
        for (int m = 0; m < M_SLOTS; m++) mx = fmaxf(mx, s[m]);
        float sum = 0.0f;
        #pragma unroll
        for (int m = 0; m < M_SLOTS; m++) { s[m] = __expf(s[m] - mx); sum += s[m]; }
        float inv = 1.0f / sum;
        #pragma unroll
        for (int m = 0; m < M_SLOTS; m++) p_loc[m] = s[m] * inv;
    }

    // broadcast: p[r][m] = lane r's p_loc[m]
    float p[4][M_SLOTS];
    #pragma unroll
    for (int r = 0; r < 4; r++)
        #pragma unroll
        for (int m = 0; m < M_SLOTS; m++)
            p[r][m] = __shfl_sync(0xFFFFFFFFu, p_loc[m], r);

    const float4* __restrict__ m4 = (const float4*)mem;
    float4* __restrict__ o0 = (float4*)(out + (size_t)(row0 + 0) * HW) + base4;
    float4* __restrict__ o1 = (float4*)(out + (size_t)(row0 + 1) * HW) + base4;
    float4* __restrict__ o2 = (float4*)(out + (size_t)(row0 + 2) * HW) + base4;
    float4* __restrict__ o3 = (float4*)(out + (size_t)(row0 + 3) * HW) + base4;

    for (int j = lane; j < KC4; j += 32) {
        float4 a0 = {0.f, 0.f, 0.f, 0.f};
        float4 a1 = {0.f, 0.f, 0.f, 0.f};
        float4 a2 = {0.f, 0.f, 0.f, 0.f};
        float4 a3 = {0.f, 0.f, 0.f, 0.f};
        #pragma unroll
        for (int m = 0; m < M_SLOTS; m++) {
            float4 w = __ldg(&m4[(size_t)m * HW4 + base4 + j]);
            a0.x = fmaf(p[0][m], w.x, a0.x); a0.y = fmaf(p[0][m], w.y, a0.y);
            a0.z = fmaf(p[0][m], w.z, a0.z); a0.w = fmaf(p[0][m], w.w, a0.w);
            a1.x = fmaf(p[1][m], w.x, a1.x); a1.y = fmaf(p[1][m], w.y, a1.y);
            a1.z = fmaf(p[1][m], w.z, a1.z); a1.w = fmaf(p[1][m], w.w, a1.w);
            a2.x = fmaf(p[2][m], w.x, a2.x); a2.y = fmaf(p[2][m], w.y, a2.y);
            a2.z = fmaf(p[2][m], w.z, a2.z); a2.w = fmaf(p[2][m], w.w, a2.w);
            a3.x = fmaf(p[3][m], w.x, a3.x); a3.y = fmaf(p[3][m], w.y, a3.y);
            a3.z = fmaf(p[3][m], w.z, a3.z); a3.w = fmaf(p[3][m], w.w, a3.w);
        }
        o0[j] = a0;
        o1[j] = a1;
        o2[j] = a2;
        o3[j] = a3;
    }
}

extern "C" void kernel_launch(void* const* d_in, const int* in_sizes, int n_in,
                              void* d_out, int out_size) {
    const float* x   = (const float*)d_in[0];   // [32,256,88,88]
    const float* mem = (const float*)d_in[1];   // [10,88,88]
    float* out = (float*)d_out;

    dim3 grid(ROWS / RPB, NCH);   // 256 x 8 = 2048 blocks
    k1_scores<<<grid, NT>>>(x, mem);
    k3_value<<<grid, NT>>>(mem, out);
}